// round 2
// baseline (speedup 1.0000x reference)
#include <cuda_runtime.h>
#include <cstddef>

// Shapes (from reference): B=16, N=4096, C_sp=768, C_fd=512, H=8, D=96.
// softmax over a size-1 axis == 1.0 exactly, so:
//   out[b,n,:] = ((freq[b,:] @ Wv^T + bv) @ Wo^T + bo)   -- independent of n.
// Q / Wq / bq / Wk / bk / spatial_tokens are mathematically dead.

#define CSP 768
#define CFD 512
#define MAXB 64

__device__ float g_V[MAXB * CSP];
__device__ float g_O[MAXB * CSP];

// ---------------------------------------------------------------------------
// Kernel 1: V[b,c] = bv[c] + sum_j freq[b,j] * Wv[c,j]
// grid (B, CSP/128), block 128 (4 warps). Warp-collective dot, coalesced Wv reads.
// ---------------------------------------------------------------------------
__global__ void __launch_bounds__(128) proj_v_kernel(
    const float* __restrict__ freq,
    const float* __restrict__ Wv,
    const float* __restrict__ bv)
{
    const int b = blockIdx.x;
    const int cbase = blockIdx.y * 128;
    __shared__ float sf[CFD];
    for (int i = threadIdx.x; i < CFD; i += 128)
        sf[i] = freq[(size_t)b * CFD + i];
    __syncthreads();

    const int warp = threadIdx.x >> 5;
    const int lane = threadIdx.x & 31;

    #pragma unroll 4
    for (int e = 0; e < 32; ++e) {
        const int c = cbase + warp * 32 + e;
        const float* __restrict__ wrow = Wv + (size_t)c * CFD;
        float s = 0.f;
        #pragma unroll
        for (int j = lane; j < CFD; j += 32)
            s += sf[j] * wrow[j];
        #pragma unroll
        for (int o = 16; o; o >>= 1)
            s += __shfl_xor_sync(0xffffffffu, s, o);
        if (lane == 0)
            g_V[b * CSP + c] = s + bv[c];
    }
}

// ---------------------------------------------------------------------------
// Kernel 2: O[b,c] = bo[c] + sum_j V[b,j] * Wo[c,j]
// Same structure, inner dim CSP=768.
// ---------------------------------------------------------------------------
__global__ void __launch_bounds__(128) proj_o_kernel(
    const float* __restrict__ Wo,
    const float* __restrict__ bo)
{
    const int b = blockIdx.x;
    const int cbase = blockIdx.y * 128;
    __shared__ float sv[CSP];
    for (int i = threadIdx.x; i < CSP; i += 128)
        sv[i] = g_V[b * CSP + i];
    __syncthreads();

    const int warp = threadIdx.x >> 5;
    const int lane = threadIdx.x & 31;

    #pragma unroll 4
    for (int e = 0; e < 32; ++e) {
        const int c = cbase + warp * 32 + e;
        const float* __restrict__ wrow = Wo + (size_t)c * CSP;
        float s = 0.f;
        #pragma unroll
        for (int j = lane; j < CSP; j += 32)
            s += sv[j] * wrow[j];
        #pragma unroll
        for (int o = 16; o; o >>= 1)
            s += __shfl_xor_sync(0xffffffffu, s, o);
        if (lane == 0)
            g_O[b * CSP + c] = s + bo[c];
    }
}

// ---------------------------------------------------------------------------
// Kernel 3: broadcast O[b,:] to out[b, n0..n0+ROWS, :].
// 192 threads/block, each owns ONE float4 of the O row (held in registers),
// then issues a pure STG.128 loop. This is a pure-store-bandwidth kernel:
// O is read exactly once per block; the 192 MiB of output is the only traffic.
// ---------------------------------------------------------------------------
#define BCAST_ROWS 16

__global__ void __launch_bounds__(192) bcast_kernel(
    float4* __restrict__ out, int N)
{
    const int b = blockIdx.x;
    const int n0 = blockIdx.y * BCAST_ROWS;
    const int c4 = threadIdx.x;              // 0..191, CSP/4 = 192

    const float4 v = reinterpret_cast<const float4*>(g_O)[b * (CSP / 4) + c4];

    float4* base = out + ((size_t)b * N + n0) * (CSP / 4) + c4;
    const int rows = min(BCAST_ROWS, N - n0);
    #pragma unroll
    for (int r = 0; r < BCAST_ROWS; ++r) {
        if (r < rows)
            base[(size_t)r * (CSP / 4)] = v;
    }
}

// ---------------------------------------------------------------------------
// Launch. Inputs (metadata order):
//  0 spatial_tokens [B,N,CSP]  (dead)
//  1 freq_token     [B,CFD]
//  2 Wq, 3 bq, 4 Wk, 5 bk      (dead)
//  6 Wv [CSP,CFD], 7 bv [CSP]
//  8 Wo [CSP,CSP], 9 bo [CSP]
// ---------------------------------------------------------------------------
extern "C" void kernel_launch(void* const* d_in, const int* in_sizes, int n_in,
                              void* d_out, int out_size)
{
    const float* freq = (const float*)d_in[1];
    const float* Wv   = (const float*)d_in[6];
    const float* bv   = (const float*)d_in[7];
    const float* Wo   = (const float*)d_in[8];
    const float* bo   = (const float*)d_in[9];

    const int B = in_sizes[1] / CFD;                 // 16
    const int N = in_sizes[0] / (B * CSP);           // 4096

    proj_v_kernel<<<dim3(B, CSP / 128), 128>>>(freq, Wv, bv);
    proj_o_kernel<<<dim3(B, CSP / 128), 128>>>(Wo, bo);

    const int nBlocksY = (N + BCAST_ROWS - 1) / BCAST_ROWS;
    bcast_kernel<<<dim3(B, nBlocksY), 192>>>((float4*)d_out, N);
}

// round 4
// speedup vs baseline: 3.5452x; 3.5452x over previous
#include <cuda_runtime.h>
#include <cstddef>

// Shapes: B=16, N=4096, C_sp=768, C_fd=512, H=8, D=96.
// softmax over the size-1 KV axis == 1.0 exactly, so
//   out[b,n,:] = ((freq[b,:] @ Wv^T + bv) @ Wo^T + bo)   -- independent of n.
// Q / Wq / bq / Wk / bk / spatial_tokens are mathematically dead.

#define CSP 768
#define CFD 512
#define MAXB 64

__device__ float g_V[MAXB * CSP];
__device__ float g_O[MAXB * CSP];

// ---------------------------------------------------------------------------
// Stage 1: V[b,c] = bv[c] + dot(freq[b,:], Wv[c,:])   (inner dim 512)
// Warp-per-output: each lane does 4 independent float4 loads from Wv and
// freq (batched -> MLP~8), FFMA tree, 5-step shfl reduce. g_V referenced in
// DEVICE code only (the R3 bug was passing the symbol from host).
// ---------------------------------------------------------------------------
__global__ void __launch_bounds__(256) proj_v_kernel(
    const float* __restrict__ freq,
    const float* __restrict__ Wv,
    const float* __restrict__ bv)
{
    const int gwid = blockIdx.x * 8 + (threadIdx.x >> 5);
    const int lane = threadIdx.x & 31;
    const int b = gwid / CSP;
    const int c = gwid - b * CSP;

    const float4* __restrict__ w4 = reinterpret_cast<const float4*>(Wv + (size_t)c * CFD);
    const float4* __restrict__ x4 = reinterpret_cast<const float4*>(freq + (size_t)b * CFD);

    float s = 0.f;
    #pragma unroll
    for (int k = 0; k < CFD / 128; ++k) {            // 4 iterations
        const float4 a = x4[lane + 32 * k];
        const float4 w = w4[lane + 32 * k];
        s += a.x * w.x + a.y * w.y + a.z * w.z + a.w * w.w;
    }
    #pragma unroll
    for (int o = 16; o; o >>= 1)
        s += __shfl_xor_sync(0xffffffffu, s, o);
    if (lane == 0)
        g_V[b * CSP + c] = s + bv[c];
}

// ---------------------------------------------------------------------------
// Stage 2: O[b,c] = bo[c] + dot(V[b,:], Wo[c,:])     (inner dim 768)
// ---------------------------------------------------------------------------
__global__ void __launch_bounds__(256) proj_o_kernel(
    const float* __restrict__ Wo,
    const float* __restrict__ bo)
{
    const int gwid = blockIdx.x * 8 + (threadIdx.x >> 5);
    const int lane = threadIdx.x & 31;
    const int b = gwid / CSP;
    const int c = gwid - b * CSP;

    const float4* __restrict__ w4 = reinterpret_cast<const float4*>(Wo + (size_t)c * CSP);
    const float4* __restrict__ x4 = reinterpret_cast<const float4*>(g_V) + b * (CSP / 4);

    float s = 0.f;
    #pragma unroll
    for (int k = 0; k < CSP / 128; ++k) {            // 6 iterations
        const float4 a = x4[lane + 32 * k];
        const float4 w = w4[lane + 32 * k];
        s += a.x * w.x + a.y * w.y + a.z * w.z + a.w * w.w;
    }
    #pragma unroll
    for (int o = 16; o; o >>= 1)
        s += __shfl_xor_sync(0xffffffffu, s, o);
    if (lane == 0)
        g_O[b * CSP + c] = s + bo[c];
}

// ---------------------------------------------------------------------------
// Stage 3: broadcast O[b,:] to out[b, n0..n0+ROWS, :]. 192 threads own one
// float4 each of the O row (register-resident), then a pure evict-first
// STG.128 stream. Output written once, never re-read -> __stcs.
// ---------------------------------------------------------------------------
#define BCAST_ROWS 16

__global__ void __launch_bounds__(192) bcast_kernel(
    float4* __restrict__ out, int N)
{
    const int b = blockIdx.x;
    const int n0 = blockIdx.y * BCAST_ROWS;
    const int c4 = threadIdx.x;  // 0..191 == CSP/4

    const float4 v = reinterpret_cast<const float4*>(g_O)[b * (CSP / 4) + c4];

    float4* base = out + ((size_t)b * N + n0) * (CSP / 4) + c4;
    const int rows = min(BCAST_ROWS, N - n0);
    #pragma unroll
    for (int r = 0; r < BCAST_ROWS; ++r) {
        if (r < rows)
            __stcs(base + (size_t)r * (CSP / 4), v);
    }
}

// ---------------------------------------------------------------------------
// Inputs (metadata order):
//  0 spatial_tokens [B,N,CSP]  (dead)
//  1 freq_token     [B,CFD]
//  2 Wq, 3 bq, 4 Wk, 5 bk      (dead)
//  6 Wv [CSP,CFD], 7 bv [CSP]
//  8 Wo [CSP,CSP], 9 bo [CSP]
// ---------------------------------------------------------------------------
extern "C" void kernel_launch(void* const* d_in, const int* in_sizes, int n_in,
                              void* d_out, int out_size)
{
    const float* freq = (const float*)d_in[1];
    const float* Wv   = (const float*)d_in[6];
    const float* bv   = (const float*)d_in[7];
    const float* Wo   = (const float*)d_in[8];
    const float* bo   = (const float*)d_in[9];

    const int B = in_sizes[1] / CFD;        // 16
    const int N = in_sizes[0] / (B * CSP);  // 4096

    const int blocks = (B * CSP) / 8;       // 12288 warp-outputs, 8 warps/block
    proj_v_kernel<<<blocks, 256>>>(freq, Wv, bv);
    proj_o_kernel<<<blocks, 256>>>(Wo, bo);

    const int nBlocksY = (N + BCAST_ROWS - 1) / BCAST_ROWS;
    bcast_kernel<<<dim3(B, nBlocksY), 192>>>((float4*)d_out, N);
}

// round 5
// speedup vs baseline: 3.6061x; 1.0172x over previous
#include <cuda_runtime.h>
#include <cstddef>

// Shapes: B=16, N=4096, C_sp=768, C_fd=512, H=8, D=96.
// softmax over the size-1 KV axis == 1.0 exactly, so
//   out[b,n,:] = ((freq[b,:] @ Wv^T + bv) @ Wo^T + bo)   -- independent of n.
// Q / Wq / bq / Wk / bk / spatial_tokens are mathematically dead.

#define CSP 768
#define CFD 512
#define MAXB 64

__device__ float g_V[MAXB * CSP];
__device__ float g_O[MAXB * CSP];

// ---------------------------------------------------------------------------
// Stage 1: V[b,c] = bv[c] + dot(freq[b,:], Wv[c,:])   (inner dim 512)
// Warp-per-output: each lane does 4 independent float4 loads from Wv and
// freq (batched -> MLP~8), FFMA tree, 5-step shfl reduce. g_V referenced in
// DEVICE code only (the R3 bug was passing the symbol from host).
// ---------------------------------------------------------------------------
__global__ void __launch_bounds__(256) proj_v_kernel(
    const float* __restrict__ freq,
    const float* __restrict__ Wv,
    const float* __restrict__ bv)
{
    const int gwid = blockIdx.x * 8 + (threadIdx.x >> 5);
    const int lane = threadIdx.x & 31;
    const int b = gwid / CSP;
    const int c = gwid - b * CSP;

    const float4* __restrict__ w4 = reinterpret_cast<const float4*>(Wv + (size_t)c * CFD);
    const float4* __restrict__ x4 = reinterpret_cast<const float4*>(freq + (size_t)b * CFD);

    float s = 0.f;
    #pragma unroll
    for (int k = 0; k < CFD / 128; ++k) {            // 4 iterations
        const float4 a = x4[lane + 32 * k];
        const float4 w = w4[lane + 32 * k];
        s += a.x * w.x + a.y * w.y + a.z * w.z + a.w * w.w;
    }
    #pragma unroll
    for (int o = 16; o; o >>= 1)
        s += __shfl_xor_sync(0xffffffffu, s, o);
    if (lane == 0)
        g_V[b * CSP + c] = s + bv[c];
}

// ---------------------------------------------------------------------------
// Stage 2: O[b,c] = bo[c] + dot(V[b,:], Wo[c,:])     (inner dim 768)
// ---------------------------------------------------------------------------
__global__ void __launch_bounds__(256) proj_o_kernel(
    const float* __restrict__ Wo,
    const float* __restrict__ bo)
{
    const int gwid = blockIdx.x * 8 + (threadIdx.x >> 5);
    const int lane = threadIdx.x & 31;
    const int b = gwid / CSP;
    const int c = gwid - b * CSP;

    const float4* __restrict__ w4 = reinterpret_cast<const float4*>(Wo + (size_t)c * CSP);
    const float4* __restrict__ x4 = reinterpret_cast<const float4*>(g_V) + b * (CSP / 4);

    float s = 0.f;
    #pragma unroll
    for (int k = 0; k < CSP / 128; ++k) {            // 6 iterations
        const float4 a = x4[lane + 32 * k];
        const float4 w = w4[lane + 32 * k];
        s += a.x * w.x + a.y * w.y + a.z * w.z + a.w * w.w;
    }
    #pragma unroll
    for (int o = 16; o; o >>= 1)
        s += __shfl_xor_sync(0xffffffffu, s, o);
    if (lane == 0)
        g_O[b * CSP + c] = s + bo[c];
}

// ---------------------------------------------------------------------------
// Stage 3: broadcast O[b,:] to out[b, n0..n0+ROWS, :]. 192 threads own one
// float4 each of the O row (register-resident), then a pure evict-first
// STG.128 stream. Output written once, never re-read -> __stcs.
// ---------------------------------------------------------------------------
#define BCAST_ROWS 16

__global__ void __launch_bounds__(192) bcast_kernel(
    float4* __restrict__ out, int N)
{
    const int b = blockIdx.x;
    const int n0 = blockIdx.y * BCAST_ROWS;
    const int c4 = threadIdx.x;  // 0..191 == CSP/4

    const float4 v = reinterpret_cast<const float4*>(g_O)[b * (CSP / 4) + c4];

    float4* base = out + ((size_t)b * N + n0) * (CSP / 4) + c4;
    const int rows = min(BCAST_ROWS, N - n0);
    #pragma unroll
    for (int r = 0; r < BCAST_ROWS; ++r) {
        if (r < rows)
            __stcs(base + (size_t)r * (CSP / 4), v);
    }
}

// ---------------------------------------------------------------------------
// Inputs (metadata order):
//  0 spatial_tokens [B,N,CSP]  (dead)
//  1 freq_token     [B,CFD]
//  2 Wq, 3 bq, 4 Wk, 5 bk      (dead)
//  6 Wv [CSP,CFD], 7 bv [CSP]
//  8 Wo [CSP,CSP], 9 bo [CSP]
// ---------------------------------------------------------------------------
extern "C" void kernel_launch(void* const* d_in, const int* in_sizes, int n_in,
                              void* d_out, int out_size)
{
    const float* freq = (const float*)d_in[1];
    const float* Wv   = (const float*)d_in[6];
    const float* bv   = (const float*)d_in[7];
    const float* Wo   = (const float*)d_in[8];
    const float* bo   = (const float*)d_in[9];

    const int B = in_sizes[1] / CFD;        // 16
    const int N = in_sizes[0] / (B * CSP);  // 4096

    const int blocks = (B * CSP) / 8;       // 12288 warp-outputs, 8 warps/block
    proj_v_kernel<<<blocks, 256>>>(freq, Wv, bv);
    proj_o_kernel<<<blocks, 256>>>(Wo, bo);

    const int nBlocksY = (N + BCAST_ROWS - 1) / BCAST_ROWS;
    bcast_kernel<<<dim3(B, nBlocksY), 192>>>((float4*)d_out, N);
}